// round 9
// baseline (speedup 1.0000x reference)
#include <cuda_runtime.h>
#include <cuda_fp16.h>
#include <cstdint>

#define B_SZ    16
#define C_IN    64
#define N_POS   40962
#define C_OUT   32
#define K_CH    224                 // 7*C_OUT, permuted: k = sub*32 + o
#define NEW_N   (4*N_POS - 6)       // 163842
#define TILE_P  64
#define TILES_B 641                 // ceil(40962/64)
#define GBLK    256
#define GBLKS_B 641                 // ceil(163842/256)
#define GRID    148
#define NTHR    512

// 293 MB scratch for y' [B][N][224] fp16 (permuted channel layout)
__device__ __half g_y[(size_t)B_SZ * N_POS * K_CH];

// grid barrier state (self-resetting arrive counter; release is monotonic)
__device__ unsigned g_arrive  = 0;
__device__ unsigned g_release = 0;

// ---------------------------------------------------------------------------
// smem layout (bytes)
// ---------------------------------------------------------------------------
#define SM_XH    0        // xh [64][64] fp16 : 8192   (128B rows, SW128)
#define SM_XL    8192     // xl [64][64] fp16 : 8192
#define SM_WH    16384    // wh [224][64] fp16 : 28672
#define SM_ASF   45056    // x staging f32 [64 c][64 p] : 16384
#define SM_STAGE 61440    // epilogue stage fp16 [64][232] : 29696
#define STG_ROW_H 232
#define SM_GSM   91136    // gather transpose f32 [256][33] : 33792
#define SM_TOTAL 124928

static __device__ __forceinline__ uint32_t smem_u32(const void* p) {
    uint32_t a;
    asm("{ .reg .u64 t; cvta.to.shared.u64 t, %1; cvt.u32.u64 %0, t; }" : "=r"(a) : "l"(p));
    return a;
}
static __device__ __forceinline__ uint32_t swz(uint32_t off) {
    return off ^ ((off >> 3) & 0x70);
}
static __device__ __forceinline__ void ldsm_x4(uint32_t* a, uint32_t addr) {
    asm volatile("ldmatrix.sync.aligned.m8n8.x4.shared.b16 {%0,%1,%2,%3}, [%4];"
                 : "=r"(a[0]), "=r"(a[1]), "=r"(a[2]), "=r"(a[3]) : "r"(addr));
}
static __device__ __forceinline__ void ldsm_x2(uint32_t* b, uint32_t addr) {
    asm volatile("ldmatrix.sync.aligned.m8n8.x2.shared.b16 {%0,%1}, [%2];"
                 : "=r"(b[0]), "=r"(b[1]) : "r"(addr));
}
static __device__ __forceinline__ void mma_f16(float* d, const uint32_t* a, const uint32_t* b) {
    asm volatile("mma.sync.aligned.m16n8k16.row.col.f32.f16.f16.f32 "
                 "{%0,%1,%2,%3}, {%4,%5,%6,%7}, {%8,%9}, {%0,%1,%2,%3};"
                 : "+f"(d[0]), "+f"(d[1]), "+f"(d[2]), "+f"(d[3])
                 : "r"(a[0]), "r"(a[1]), "r"(a[2]), "r"(a[3]), "r"(b[0]), "r"(b[1]));
}
#define NB(id) asm volatile("bar.sync %0, 256;" :: "r"(id) : "memory")

// ---------------------------------------------------------------------------
// Fused persistent kernel.
// Warps 0-7 : GEMM  y'[b][p][n] = sum_c x[b][c][p]*wh[n][c] (+xl seg) + bias
// Warps 8-15: gather out[b-1] from y'[b-1]
// Grid barrier between steps guarantees y'[s] complete before gather(s).
// ---------------------------------------------------------------------------
__global__ void __launch_bounds__(NTHR, 1)
fused_kernel(const float* __restrict__ x,
             const float* __restrict__ W,
             const float* __restrict__ bias,
             const int*   __restrict__ top,
             const int*   __restrict__ down,
             float*       __restrict__ out)
{
    extern __shared__ char sm[];
    const uint32_t smb = smem_u32(sm);
    float*  Asf = (float*)(sm + SM_ASF);
    __half* stg = (__half*)(sm + SM_STAGE);
    float (*gsm)[33] = (float(*)[33])(sm + SM_GSM);

    const int tid = threadIdx.x;
    const int w   = tid >> 5;
    const int l   = tid & 31;
    const int bid = blockIdx.x;

    unsigned rel_base = 0;
    if (tid == 0) rel_base = atomicAdd(&g_release, 0);

    // --- one-time: build wh (permuted, fp16, swizzled); all 512 threads ---
    for (int idx = tid; idx < K_CH * C_IN; idx += NTHR) {
        int n = idx >> 6, c = idx & 63;
        int rw = (n & 31) * 7 + (n >> 5);
        uint32_t off = swz((uint32_t)(n * 128 + c * 2));
        *(__half*)(sm + SM_WH + off) = __float2half_rn(W[rw * C_IN + c]);
    }

    // --- gemm-warp private setup ---
    const int wm = w & 1;            // 0..1 : 32-row group within 64-row tile
    const int wn = w >> 1;           // 0..3 : 56-col group (gemm warps only)
    float2 bb[7];
    if (w < 8) {
        int nbase = wn * 56 + (l & 3) * 2;
        #pragma unroll
        for (int nt = 0; nt < 7; nt++) {
            int n0 = nbase + nt * 8;
            int n1 = n0 + 1;
            bb[nt].x = bias[(n0 & 31) * 7 + (n0 >> 5)];
            bb[nt].y = bias[(n1 & 31) * 7 + (n1 >> 5)];
        }
    }
    const uint32_t a_lane = (uint32_t)((wm * 32 + (l & 15)) * 128 + (l >> 4) * 16);
    const uint32_t b_lane = (uint32_t)((wn * 56 + (l & 7)) * 128 + ((l >> 3) & 1) * 16);
    const int cp  = tid & 63;        // convert row (gemm group: tid 0..255)
    const int cc0 = (tid >> 6) * 16; // convert c range

    // gather-warp private setup
    const int tid2 = tid - 256;      // 0..255 for gather group
    const int w2   = tid2 >> 5;
    const int g8   = l >> 2;         // m within octet
    const int l4   = l & 3;          // uint4 slot

    __syncthreads();

    for (int step = 0; step <= B_SZ; step++) {
        if (step > 0) {
            // ---- grid barrier: all y'[step-1] writes chip-visible ----
            __syncthreads();
            if (tid == 0) {
                __threadfence();
                unsigned old = atomicAdd(&g_arrive, 1);
                if (old == GRID - 1) {
                    atomicExch(&g_arrive, 0);
                    __threadfence();
                    atomicAdd(&g_release, 1);
                } else {
                    while (atomicAdd(&g_release, 0) - rel_base < (unsigned)step)
                        __nanosleep(64);
                }
                __threadfence();
            }
            __syncthreads();
        }

        if (w < 8) {
            // ================= GEMM group: compute y'[step] =================
            if (step < B_SZ) {
                const int b = step;
                const float* xb = x + (size_t)b * C_IN * N_POS;
                __half* yb = g_y + (size_t)b * N_POS * K_CH;

                for (int t = bid; t < TILES_B; t += GRID) {
                    const int p0 = t * TILE_P;

                    // stage Asf[c][p] (64x64)
                    #pragma unroll
                    for (int it = 0; it < 16; it++) {
                        int idx = it * 256 + tid;
                        int c = idx >> 6, p = idx & 63;
                        Asf[idx] = (p0 + p < N_POS) ? xb[(size_t)c * N_POS + p0 + p] : 0.0f;
                    }
                    NB(1);

                    // convert -> xh/xl fp16 swizzled
                    #pragma unroll
                    for (int blk = 0; blk < 2; blk++) {
                        int cb = cc0 + blk * 8;
                        float xv[8];
                        #pragma unroll
                        for (int j = 0; j < 8; j++) xv[j] = Asf[(cb + j) * 64 + cp];
                        uint32_t hi[4], lo[4];
                        #pragma unroll
                        for (int q = 0; q < 4; q++) {
                            float x0 = xv[2 * q], x1 = xv[2 * q + 1];
                            half2 h = __floats2half2_rn(x0, x1);
                            float2 hf = __half22float2(h);
                            half2 lw = __floats2half2_rn(x0 - hf.x, x1 - hf.y);
                            hi[q] = *(uint32_t*)&h;
                            lo[q] = *(uint32_t*)&lw;
                        }
                        uint32_t off = swz((uint32_t)(cp * 128 + cb * 2));
                        *(uint4*)(sm + SM_XH + off) = make_uint4(hi[0], hi[1], hi[2], hi[3]);
                        *(uint4*)(sm + SM_XL + off) = make_uint4(lo[0], lo[1], lo[2], lo[3]);
                    }
                    NB(1);

                    // MMA: 4 k16-chunks, 2 segments sharing B fragments
                    float d[2][7][4];
                    #pragma unroll
                    for (int mt = 0; mt < 2; mt++)
                        #pragma unroll
                        for (int nt = 0; nt < 7; nt++)
                            #pragma unroll
                            for (int q = 0; q < 4; q++) d[mt][nt][q] = 0.0f;

                    #pragma unroll
                    for (int kci = 0; kci < 4; kci++) {
                        const uint32_t kcb = kci * 32;
                        uint32_t bfr[7][2];
                        #pragma unroll
                        for (int nt = 0; nt < 7; nt++)
                            ldsm_x2(bfr[nt], smb + SM_WH + swz(b_lane + (uint32_t)nt * 1024 + kcb));
                        uint32_t ah[2][4], al[2][4];
                        ldsm_x4(ah[0], smb + SM_XH + swz(a_lane + kcb));
                        ldsm_x4(ah[1], smb + SM_XH + swz(a_lane + 2048 + kcb));
                        ldsm_x4(al[0], smb + SM_XL + swz(a_lane + kcb));
                        ldsm_x4(al[1], smb + SM_XL + swz(a_lane + 2048 + kcb));
                        #pragma unroll
                        for (int nt = 0; nt < 7; nt++) {
                            mma_f16(d[0][nt], ah[0], bfr[nt]);
                            mma_f16(d[1][nt], ah[1], bfr[nt]);
                            mma_f16(d[0][nt], al[0], bfr[nt]);
                            mma_f16(d[1][nt], al[1], bfr[nt]);
                        }
                    }

                    // epilogue: bias + fp16 -> smem stage
                    {
                        const int qrow = l >> 2;
                        const int ncol = wn * 56 + (l & 3) * 2;
                        #pragma unroll
                        for (int mt = 0; mt < 2; mt++) {
                            #pragma unroll
                            for (int rsel = 0; rsel < 2; rsel++) {
                                int row = wm * 32 + mt * 16 + rsel * 8 + qrow;
                                __half* sr = stg + row * STG_ROW_H + ncol;
                                #pragma unroll
                                for (int nt = 0; nt < 7; nt++) {
                                    float vx = d[mt][nt][rsel * 2 + 0] + bb[nt].x;
                                    float vy = d[mt][nt][rsel * 2 + 1] + bb[nt].y;
                                    *(half2*)(sr + nt * 8) = __floats2half2_rn(vx, vy);
                                }
                            }
                        }
                    }
                    NB(1);

                    // coalesced writeback: warp w -> rows w*8..+7 (448B rows)
                    if (l < 28) {
                        #pragma unroll
                        for (int r = 0; r < 8; r++) {
                            int row = w * 8 + r;
                            int gp = p0 + row;
                            if (gp < N_POS) {
                                uint4 v = *(const uint4*)(stg + row * STG_ROW_H + l * 8);
                                *(uint4*)(yb + (size_t)gp * K_CH + l * 8) = v;
                            }
                        }
                    }
                    NB(1);   // stage reads done before next tile's epilogue STS
                }
            }
        } else {
            // ================= gather group: out[step-1] from y'[step-1] ====
            if (step > 0) {
                const int b = step - 1;
                const __half* yb = g_y + (size_t)b * N_POS * K_CH;
                float* ob = out + (size_t)b * C_OUT * NEW_N;

                for (int blk = bid; blk < GBLKS_B; blk += GRID) {
                    const int m0 = blk * GBLK;
                    NB(2);   // gsm reusable (prev block's reads done)

                    #pragma unroll
                    for (int i = 0; i < 4; i++) {
                        int mm = w2 * 32 + i * 8 + g8;
                        int m  = m0 + mm;
                        float vf[8];
                        #pragma unroll
                        for (int j = 0; j < 8; j++) vf[j] = 0.0f;
                        if (m < NEW_N) {
                            if (m < N_POS) {
                                int j   = __ldg(top + m);
                                int sub = j / N_POS;
                                int p   = j - sub * N_POS;
                                uint4 v = *(const uint4*)(yb + (size_t)p * K_CH + sub * 32 + l4 * 8);
                                const half2* h = (const half2*)&v;
                                #pragma unroll
                                for (int q = 0; q < 4; q++) {
                                    float2 f = __half22float2(h[q]);
                                    vf[2 * q] = f.x; vf[2 * q + 1] = f.y;
                                }
                            } else {
                                int2 jj = *(const int2*)(down + 2 * (m - N_POS));
                                int s0 = jj.x / N_POS, p0i = jj.x - s0 * N_POS;
                                int s1 = jj.y / N_POS, p1i = jj.y - s1 * N_POS;
                                uint4 v0 = *(const uint4*)(yb + (size_t)p0i * K_CH + s0 * 32 + l4 * 8);
                                uint4 v1 = *(const uint4*)(yb + (size_t)p1i * K_CH + s1 * 32 + l4 * 8);
                                const half2* h0 = (const half2*)&v0;
                                const half2* h1 = (const half2*)&v1;
                                #pragma unroll
                                for (int q = 0; q < 4; q++) {
                                    float2 f0 = __half22float2(h0[q]);
                                    float2 f1 = __half22float2(h1[q]);
                                    vf[2 * q]     = 0.5f * (f0.x + f1.x);
                                    vf[2 * q + 1] = 0.5f * (f0.y + f1.y);
                                }
                            }
                        }
                        float* s = &gsm[mm][l4 * 8];
                        #pragma unroll
                        for (int j = 0; j < 8; j++) s[j] = vf[j];
                    }
                    NB(2);

                    // out[b][o][m], float2 along m
                    #pragma unroll
                    for (int it = 0; it < 16; it++) {
                        int idx = it * 256 + tid2;
                        int o = idx >> 7;
                        int q = idx & 127;
                        int m = m0 + 2 * q;
                        if (m < NEW_N) {
                            float2 v = make_float2(gsm[2 * q][o], gsm[2 * q + 1][o]);
                            *(float2*)(ob + (size_t)o * NEW_N + m) = v;
                        }
                    }
                }
            }
        }
    }
}

// ---------------------------------------------------------------------------
extern "C" void kernel_launch(void* const* d_in, const int* in_sizes, int n_in,
                              void* d_out, int out_size)
{
    const float* x    = (const float*)d_in[0];
    const float* W    = (const float*)d_in[1];
    const float* bias = (const float*)d_in[2];
    const int*   top  = (const int*)d_in[3];
    const int*   down = (const int*)d_in[4];
    float* out = (float*)d_out;

    cudaFuncSetAttribute(fused_kernel,
                         cudaFuncAttributeMaxDynamicSharedMemorySize, SM_TOTAL);

    fused_kernel<<<GRID, NTHR, SM_TOTAL>>>(x, W, bias, top, down, out);
}

// round 10
// speedup vs baseline: 1.5641x; 1.5641x over previous
#include <cuda_runtime.h>
#include <cuda_fp16.h>
#include <cstdint>

#define B_SZ    16
#define C_IN    64
#define N_POS   40962
#define C_OUT   32
#define K_CH    224                 // 7*C_OUT, permuted: k = sub*32 + o
#define NEW_N   (4*N_POS - 6)       // 163842
#define TILE_P  128
#define TILES_PER_B 321             // ceil(40962/128)
#define WORK_ITEMS (B_SZ * TILES_PER_B)   // 5136
#define GEMM_GRID 148
#define GEMM_THREADS 512

// 293 MB scratch for y' [B][N][224] fp16 (permuted channel layout)
__device__ __half g_y[(size_t)B_SZ * N_POS * K_CH];

// ---------------------------------------------------------------------------
// smem layout (bytes). fp16 tiles are [row][64] = 128 B/row, SW128 swizzle.
// ---------------------------------------------------------------------------
#define SM_XH    0        // xh [128][64] fp16 : 16384
#define SM_WH    16384    // wh [224][64] fp16 : 28672
#define SM_ASF   45056    // x staging f32 [64][128] : 32768
#define SM_STAGE 77824    // epilogue stage fp16 [128][232] : 59392 (464B rows)
#define STG_ROW_H 232
#define SM_TOTAL 137216

static __device__ __forceinline__ uint32_t smem_u32(const void* p) {
    uint32_t a;
    asm("{ .reg .u64 t; cvta.to.shared.u64 t, %1; cvt.u32.u64 %0, t; }" : "=r"(a) : "l"(p));
    return a;
}
static __device__ __forceinline__ uint32_t swz(uint32_t off) {
    return off ^ ((off >> 3) & 0x70);
}
static __device__ __forceinline__ void ldsm_x4(uint32_t* a, uint32_t addr) {
    asm volatile("ldmatrix.sync.aligned.m8n8.x4.shared.b16 {%0,%1,%2,%3}, [%4];"
                 : "=r"(a[0]), "=r"(a[1]), "=r"(a[2]), "=r"(a[3]) : "r"(addr));
}
static __device__ __forceinline__ void ldsm_x2(uint32_t* b, uint32_t addr) {
    asm volatile("ldmatrix.sync.aligned.m8n8.x2.shared.b16 {%0,%1}, [%2];"
                 : "=r"(b[0]), "=r"(b[1]) : "r"(addr));
}
static __device__ __forceinline__ void mma_f16(float* d, const uint32_t* a, const uint32_t* b) {
    asm volatile("mma.sync.aligned.m16n8k16.row.col.f32.f16.f16.f32 "
                 "{%0,%1,%2,%3}, {%4,%5,%6,%7}, {%8,%9}, {%0,%1,%2,%3};"
                 : "+f"(d[0]), "+f"(d[1]), "+f"(d[2]), "+f"(d[3])
                 : "r"(a[0]), "r"(a[1]), "r"(a[2]), "r"(a[3]), "r"(b[0]), "r"(b[1]));
}

// ---------------------------------------------------------------------------
// Persistent HMMA GEMM: y'[b][p][n] = sum_c x[b][c][p]*wh[n][c] + bias(n)
// Single fp16 segment (HMMA products exact, fp32 accum -> ~2-3e-4 rel err).
// 512 threads / 16 warps. wm=w&3 -> rows wm*32..+31; wn=w>>2 -> cols
// wn*56..+55. Acc d[2][7][4].
// ---------------------------------------------------------------------------
__global__ void __launch_bounds__(GEMM_THREADS, 1)
gemm_hmma_kernel(const float* __restrict__ x,
                 const float* __restrict__ W,
                 const float* __restrict__ bias)
{
    extern __shared__ char sm[];
    const uint32_t smb = smem_u32(sm);
    float*  Asf = (float*)(sm + SM_ASF);
    __half* stg = (__half*)(sm + SM_STAGE);

    const int tid = threadIdx.x;
    const int w   = tid >> 5;
    const int l   = tid & 31;
    const int wm  = w & 3;
    const int wn  = w >> 2;          // 0..3

    // --- one-time: build wh (permuted, fp16, swizzled) ---
    for (int idx = tid; idx < K_CH * C_IN; idx += GEMM_THREADS) {
        int n = idx >> 6, c = idx & 63;
        int rw = (n & 31) * 7 + (n >> 5);
        uint32_t off = swz((uint32_t)(n * 128 + c * 2));
        *(__half*)(sm + SM_WH + off) = __float2half_rn(W[rw * C_IN + c]);
    }

    // --- per-thread bias regs: n = wn*56 + nt*8 + 2*(l&3) ---
    float2 bb[7];
    {
        int nbase = wn * 56 + (l & 3) * 2;
        #pragma unroll
        for (int nt = 0; nt < 7; nt++) {
            int n0 = nbase + nt * 8;
            int n1 = n0 + 1;
            bb[nt].x = bias[(n0 & 31) * 7 + (n0 >> 5)];
            bb[nt].y = bias[(n1 & 31) * 7 + (n1 >> 5)];
        }
    }

    const uint32_t a_lane = (uint32_t)((wm * 32 + (l & 15)) * 128 + (l >> 4) * 16);
    const uint32_t b_lane = (uint32_t)((wn * 56 + (l & 7)) * 128 + ((l >> 3) & 1) * 16);

    const int cp  = tid & 127;
    const int cc0 = (tid >> 7) * 16;

    int item = blockIdx.x;

    // prologue: stage first tile
    {
        int b = item / TILES_PER_B, t = item - (item / TILES_PER_B) * TILES_PER_B;
        const float* xb = x + (size_t)b * C_IN * N_POS + (size_t)t * TILE_P;
        int p0 = t * TILE_P;
        #pragma unroll
        for (int it2 = 0; it2 < 16; it2++) {
            int idx = it2 * GEMM_THREADS + tid;
            int c = idx >> 7, p = idx & 127;
            Asf[idx] = (p0 + p < N_POS) ? xb[(size_t)c * N_POS + p] : 0.0f;
        }
    }
    __syncthreads();

    for (; item < WORK_ITEMS; item += GEMM_GRID) {
        const int b  = item / TILES_PER_B;
        const int t  = item - b * TILES_PER_B;
        const int p0 = t * TILE_P;
        __half* yb = g_y + (size_t)b * N_POS * K_CH;

        // --- convert: xh [p][c] fp16, swizzled (reads Asf) ---
        #pragma unroll
        for (int blk = 0; blk < 2; blk++) {
            int cb = cc0 + blk * 8;
            float xv[8];
            #pragma unroll
            for (int j = 0; j < 8; j++) xv[j] = Asf[(cb + j) * TILE_P + cp];
            uint32_t hi[4];
            #pragma unroll
            for (int q = 0; q < 4; q++) {
                half2 h = __floats2half2_rn(xv[2 * q], xv[2 * q + 1]);
                hi[q] = *(uint32_t*)&h;
            }
            uint32_t off = swz((uint32_t)(cp * 128 + cb * 2));
            *(uint4*)(sm + SM_XH + off) = make_uint4(hi[0], hi[1], hi[2], hi[3]);
        }
        __syncthreads();   // xh ready; Asf reads complete

        // --- prefetch next tile's x into Asf (overlaps MMA + epilogue) ---
        {
            int nxt = item + GEMM_GRID;
            if (nxt < WORK_ITEMS) {
                int nb = nxt / TILES_PER_B, ntl = nxt - nb * TILES_PER_B;
                const float* xb = x + (size_t)nb * C_IN * N_POS + (size_t)ntl * TILE_P;
                int np0 = ntl * TILE_P;
                #pragma unroll
                for (int it2 = 0; it2 < 16; it2++) {
                    int idx = it2 * GEMM_THREADS + tid;
                    int c = idx >> 7, p = idx & 127;
                    Asf[idx] = (np0 + p < N_POS) ? xb[(size_t)c * N_POS + p] : 0.0f;
                }
            }
        }

        // --- MMA: 4 k16-chunks, single segment ---
        float d[2][7][4];
        #pragma unroll
        for (int mt = 0; mt < 2; mt++)
            #pragma unroll
            for (int nt = 0; nt < 7; nt++)
                #pragma unroll
                for (int q = 0; q < 4; q++) d[mt][nt][q] = 0.0f;

        #pragma unroll
        for (int kci = 0; kci < 4; kci++) {
            const uint32_t kcb = kci * 32;
            uint32_t bfr[7][2];
            #pragma unroll
            for (int nt = 0; nt < 7; nt++)
                ldsm_x2(bfr[nt], smb + SM_WH + swz(b_lane + (uint32_t)nt * 1024 + kcb));
            uint32_t ah[2][4];
            ldsm_x4(ah[0], smb + SM_XH + swz(a_lane + kcb));
            ldsm_x4(ah[1], smb + SM_XH + swz(a_lane + 2048 + kcb));
            #pragma unroll
            for (int nt = 0; nt < 7; nt++) {
                mma_f16(d[0][nt], ah[0], bfr[nt]);
                mma_f16(d[1][nt], ah[1], bfr[nt]);
            }
        }

        // --- epilogue stage: bias + fp16 pack -> smem ---
        {
            const int qrow = l >> 2;
            const int ncol = wn * 56 + (l & 3) * 2;
            #pragma unroll
            for (int mt = 0; mt < 2; mt++) {
                #pragma unroll
                for (int rsel = 0; rsel < 2; rsel++) {
                    int row = wm * 32 + mt * 16 + rsel * 8 + qrow;
                    __half* sr = stg + row * STG_ROW_H + ncol;
                    #pragma unroll
                    for (int nt = 0; nt < 7; nt++) {
                        float vx = d[mt][nt][rsel * 2 + 0] + bb[nt].x;
                        float vy = d[mt][nt][rsel * 2 + 1] + bb[nt].y;
                        *(half2*)(sr + nt * 8) = __floats2half2_rn(vx, vy);
                    }
                }
            }
        }
        __syncthreads();

        // --- coalesced writeback: warp w -> rows w*8..+7 (448B rows) ---
        if (l < 28) {
            #pragma unroll
            for (int r = 0; r < 8; r++) {
                int row = w * 8 + r;
                int gp = p0 + row;
                if (gp < N_POS) {
                    uint4 v = *(const uint4*)(stg + row * STG_ROW_H + l * 8);
                    *(uint4*)(yb + (size_t)gp * K_CH + l * 8) = v;
                }
            }
        }
        __syncthreads();
    }
}

// ---------------------------------------------------------------------------
// Kernel 2: gather v3 — batched loads for MLP.
// Phase 1: decode all 4 octets' indices. Phase 2: issue ALL value loads
// (4-8 uint4 in flight per thread). Phase 3: convert + STS. Then transpose out.
// ---------------------------------------------------------------------------
#define GM 256

__global__ void __launch_bounds__(256, 3)
gather_kernel(const int* __restrict__ top,
              const int* __restrict__ down,
              float* __restrict__ out)
{
    __shared__ float smx[GM][33];
    const int b    = blockIdx.y;
    const int m0   = blockIdx.x * GM;
    const int tid  = threadIdx.x;
    const int lane = tid & 31;
    const int w    = tid >> 5;
    const int g8   = lane >> 2;    // 0..7 : m within octet
    const int l4   = lane & 3;     // 0..3 : uint4 slot (8 halves)

    const __half* yb = g_y + (size_t)b * N_POS * K_CH;

    // --- phase 1: index loads (4 per thread, batched) ---
    int jx[4], jy[4];
    #pragma unroll
    for (int i = 0; i < 4; i++) {
        int m = m0 + w * 32 + i * 8 + g8;
        jx[i] = -1; jy[i] = -1;
        if (m < NEW_N) {
            if (m < N_POS) {
                jx[i] = __ldg(top + m);
            } else {
                int2 jj = *(const int2*)(down + 2 * (m - N_POS));
                jx[i] = jj.x; jy[i] = jj.y;
            }
        }
    }

    // --- phase 2: value loads (up to 8 uint4 in flight) ---
    uint4 v0[4], v1[4];
    #pragma unroll
    for (int i = 0; i < 4; i++) {
        v0[i] = make_uint4(0u, 0u, 0u, 0u);
        if (jx[i] >= 0) {
            int s = jx[i] / N_POS, p = jx[i] - s * N_POS;
            v0[i] = *(const uint4*)(yb + (size_t)p * K_CH + s * 32 + l4 * 8);
        }
    }
    #pragma unroll
    for (int i = 0; i < 4; i++) {
        if (jy[i] >= 0) {
            int s = jy[i] / N_POS, p = jy[i] - s * N_POS;
            v1[i] = *(const uint4*)(yb + (size_t)p * K_CH + s * 32 + l4 * 8);
        }
    }

    // --- phase 3: convert + STS ---
    #pragma unroll
    for (int i = 0; i < 4; i++) {
        int mm = w * 32 + i * 8 + g8;
        float vf[8];
        const half2* h0 = (const half2*)&v0[i];
        #pragma unroll
        for (int q = 0; q < 4; q++) {
            float2 f = __half22float2(h0[q]);
            vf[2 * q] = f.x; vf[2 * q + 1] = f.y;
        }
        if (jy[i] >= 0) {
            const half2* h1 = (const half2*)&v1[i];
            #pragma unroll
            for (int q = 0; q < 4; q++) {
                float2 f = __half22float2(h1[q]);
                vf[2 * q]     = 0.5f * (vf[2 * q] + f.x);
                vf[2 * q + 1] = 0.5f * (vf[2 * q + 1] + f.y);
            }
        }
        float* s = &smx[mm][l4 * 8];
        #pragma unroll
        for (int j = 0; j < 8; j++) s[j] = vf[j];
    }
    __syncthreads();

    // --- transpose write: out[b][o][m], float2 along m ---
    float* ob = out + (size_t)b * C_OUT * NEW_N;
    #pragma unroll
    for (int it = 0; it < C_OUT * (GM / 2) / 256; it++) {
        int idx = it * 256 + tid;
        int o = idx >> 7;
        int q = idx & 127;
        int m = m0 + 2 * q;
        if (m < NEW_N) {
            float2 v = make_float2(smx[2 * q][o], smx[2 * q + 1][o]);
            *(float2*)(ob + (size_t)o * NEW_N + m) = v;
        }
    }
}

// ---------------------------------------------------------------------------
extern "C" void kernel_launch(void* const* d_in, const int* in_sizes, int n_in,
                              void* d_out, int out_size)
{
    const float* x    = (const float*)d_in[0];
    const float* W    = (const float*)d_in[1];
    const float* bias = (const float*)d_in[2];
    const int*   top  = (const int*)d_in[3];
    const int*   down = (const int*)d_in[4];
    float* out = (float*)d_out;

    cudaFuncSetAttribute(gemm_hmma_kernel,
                         cudaFuncAttributeMaxDynamicSharedMemorySize, SM_TOTAL);

    gemm_hmma_kernel<<<GEMM_GRID, GEMM_THREADS, SM_TOTAL>>>(x, W, bias);

    dim3 g2((NEW_N + GM - 1) / GM, B_SZ);   // (641, 16)
    gather_kernel<<<g2, 256>>>(top, down, out);
}

// round 11
// speedup vs baseline: 1.7115x; 1.0943x over previous
#include <cuda_runtime.h>
#include <cuda_fp16.h>
#include <cstdint>

#define B_SZ    16
#define C_IN    64
#define N_POS   40962
#define C_OUT   32
#define K_CH    224                 // 7*C_OUT, permuted: k = sub*32 + o
#define NEW_N   (4*N_POS - 6)       // 163842
#define TILE_P  64
#define TILES_PER_B 641             // ceil(40962/64)
#define WORK_ITEMS (B_SZ * TILES_PER_B)   // 10256
#define GEMM_GRID 296
#define GEMM_THREADS 256

// 293 MB scratch for y' [B][N][224] fp16 (permuted channel layout)
__device__ __half g_y[(size_t)B_SZ * N_POS * K_CH];

// ---------------------------------------------------------------------------
// smem layout (bytes). fp16 tiles are [row][64] = 128 B/row, SW128 swizzle.
// Total 82 KB -> 2 CTAs/SM co-resident (phase overlap across CTAs).
// ---------------------------------------------------------------------------
#define SM_XH    0        // xh [64][64] fp16 : 8192
#define SM_WH    8192     // wh [224][64] fp16 : 28672
#define SM_ASF   36864    // x staging f32 [64 c][64 p] : 16384
#define SM_STAGE 53248    // epilogue stage fp16 [64][232] : 29696 (464B rows)
#define STG_ROW_H 232
#define SM_TOTAL 82944

static __device__ __forceinline__ uint32_t smem_u32(const void* p) {
    uint32_t a;
    asm("{ .reg .u64 t; cvta.to.shared.u64 t, %1; cvt.u32.u64 %0, t; }" : "=r"(a) : "l"(p));
    return a;
}
static __device__ __forceinline__ uint32_t swz(uint32_t off) {
    return off ^ ((off >> 3) & 0x70);
}
static __device__ __forceinline__ void ldsm_x4(uint32_t* a, uint32_t addr) {
    asm volatile("ldmatrix.sync.aligned.m8n8.x4.shared.b16 {%0,%1,%2,%3}, [%4];"
                 : "=r"(a[0]), "=r"(a[1]), "=r"(a[2]), "=r"(a[3]) : "r"(addr));
}
static __device__ __forceinline__ void ldsm_x2(uint32_t* b, uint32_t addr) {
    asm volatile("ldmatrix.sync.aligned.m8n8.x2.shared.b16 {%0,%1}, [%2];"
                 : "=r"(b[0]), "=r"(b[1]) : "r"(addr));
}
static __device__ __forceinline__ void mma_f16(float* d, const uint32_t* a, const uint32_t* b) {
    asm volatile("mma.sync.aligned.m16n8k16.row.col.f32.f16.f16.f32 "
                 "{%0,%1,%2,%3}, {%4,%5,%6,%7}, {%8,%9}, {%0,%1,%2,%3};"
                 : "+f"(d[0]), "+f"(d[1]), "+f"(d[2]), "+f"(d[3])
                 : "r"(a[0]), "r"(a[1]), "r"(a[2]), "r"(a[3]), "r"(b[0]), "r"(b[1]));
}

// ---------------------------------------------------------------------------
// Persistent HMMA GEMM: y'[b][p][n] = sum_c x[b][c][p]*wh[n][c] + bias(n)
// Single fp16 segment. 256 threads / 8 warps, 64x224 tile, 2 CTAs/SM.
// wm=w&1 -> rows wm*32..+31; wn=w>>1 -> cols wn*56..+55. Acc d[2][7][4].
// ---------------------------------------------------------------------------
__global__ void __launch_bounds__(GEMM_THREADS, 2)
gemm_hmma_kernel(const float* __restrict__ x,
                 const float* __restrict__ W,
                 const float* __restrict__ bias)
{
    extern __shared__ char sm[];
    const uint32_t smb = smem_u32(sm);
    float*  Asf = (float*)(sm + SM_ASF);
    __half* stg = (__half*)(sm + SM_STAGE);

    const int tid = threadIdx.x;
    const int w   = tid >> 5;
    const int l   = tid & 31;
    const int wm  = w & 1;           // 0..1 : 32-row group
    const int wn  = w >> 1;          // 0..3 : 56-col group

    // --- one-time: build wh (permuted, fp16, swizzled) ---
    for (int idx = tid; idx < K_CH * C_IN; idx += GEMM_THREADS) {
        int n = idx >> 6, c = idx & 63;
        int rw = (n & 31) * 7 + (n >> 5);
        uint32_t off = swz((uint32_t)(n * 128 + c * 2));
        *(__half*)(sm + SM_WH + off) = __float2half_rn(W[rw * C_IN + c]);
    }

    // --- per-thread bias regs: n = wn*56 + nt*8 + 2*(l&3) ---
    float2 bb[7];
    {
        int nbase = wn * 56 + (l & 3) * 2;
        #pragma unroll
        for (int nt = 0; nt < 7; nt++) {
            int n0 = nbase + nt * 8;
            int n1 = n0 + 1;
            bb[nt].x = bias[(n0 & 31) * 7 + (n0 >> 5)];
            bb[nt].y = bias[(n1 & 31) * 7 + (n1 >> 5)];
        }
    }

    const uint32_t a_lane = (uint32_t)((wm * 32 + (l & 15)) * 128 + (l >> 4) * 16);
    const uint32_t b_lane = (uint32_t)((wn * 56 + (l & 7)) * 128 + ((l >> 3) & 1) * 16);

    const int cp  = tid & 63;        // convert row
    const int cc0 = (tid >> 6) * 16; // convert c range

    int item = blockIdx.x;

    // prologue: stage first tile
    if (item < WORK_ITEMS) {
        int b = item / TILES_PER_B, t = item - (item / TILES_PER_B) * TILES_PER_B;
        const float* xb = x + (size_t)b * C_IN * N_POS + (size_t)t * TILE_P;
        int p0 = t * TILE_P;
        #pragma unroll
        for (int it2 = 0; it2 < 16; it2++) {
            int idx = it2 * GEMM_THREADS + tid;
            int c = idx >> 6, p = idx & 63;
            Asf[idx] = (p0 + p < N_POS) ? xb[(size_t)c * N_POS + p] : 0.0f;
        }
    }
    __syncthreads();

    for (; item < WORK_ITEMS; item += GEMM_GRID) {
        const int b  = item / TILES_PER_B;
        const int t  = item - b * TILES_PER_B;
        const int p0 = t * TILE_P;
        __half* yb = g_y + (size_t)b * N_POS * K_CH;

        // --- convert: xh [p][c] fp16, swizzled (reads Asf) ---
        #pragma unroll
        for (int blk = 0; blk < 2; blk++) {
            int cb = cc0 + blk * 8;
            float xv[8];
            #pragma unroll
            for (int j = 0; j < 8; j++) xv[j] = Asf[(cb + j) * TILE_P + cp];
            uint32_t hi[4];
            #pragma unroll
            for (int q = 0; q < 4; q++) {
                half2 h = __floats2half2_rn(xv[2 * q], xv[2 * q + 1]);
                hi[q] = *(uint32_t*)&h;
            }
            uint32_t off = swz((uint32_t)(cp * 128 + cb * 2));
            *(uint4*)(sm + SM_XH + off) = make_uint4(hi[0], hi[1], hi[2], hi[3]);
        }
        __syncthreads();   // xh ready; Asf reads complete

        // --- prefetch next tile's x into Asf (overlaps MMA + epilogue) ---
        {
            int nxt = item + GEMM_GRID;
            if (nxt < WORK_ITEMS) {
                int nb = nxt / TILES_PER_B, ntl = nxt - nb * TILES_PER_B;
                const float* xb = x + (size_t)nb * C_IN * N_POS + (size_t)ntl * TILE_P;
                int np0 = ntl * TILE_P;
                #pragma unroll
                for (int it2 = 0; it2 < 16; it2++) {
                    int idx = it2 * GEMM_THREADS + tid;
                    int c = idx >> 6, p = idx & 63;
                    Asf[idx] = (np0 + p < N_POS) ? xb[(size_t)c * N_POS + p] : 0.0f;
                }
            }
        }

        // --- MMA: 4 k16-chunks, single segment ---
        float d[2][7][4];
        #pragma unroll
        for (int mt = 0; mt < 2; mt++)
            #pragma unroll
            for (int nt = 0; nt < 7; nt++)
                #pragma unroll
                for (int q = 0; q < 4; q++) d[mt][nt][q] = 0.0f;

        #pragma unroll
        for (int kci = 0; kci < 4; kci++) {
            const uint32_t kcb = kci * 32;
            uint32_t bfr[7][2];
            #pragma unroll
            for (int nt = 0; nt < 7; nt++)
                ldsm_x2(bfr[nt], smb + SM_WH + swz(b_lane + (uint32_t)nt * 1024 + kcb));
            uint32_t ah[2][4];
            ldsm_x4(ah[0], smb + SM_XH + swz(a_lane + kcb));
            ldsm_x4(ah[1], smb + SM_XH + swz(a_lane + 2048 + kcb));
            #pragma unroll
            for (int nt = 0; nt < 7; nt++) {
                mma_f16(d[0][nt], ah[0], bfr[nt]);
                mma_f16(d[1][nt], ah[1], bfr[nt]);
            }
        }

        // --- epilogue stage: bias + fp16 pack -> smem ---
        {
            const int qrow = l >> 2;
            const int ncol = wn * 56 + (l & 3) * 2;
            #pragma unroll
            for (int mt = 0; mt < 2; mt++) {
                #pragma unroll
                for (int rsel = 0; rsel < 2; rsel++) {
                    int row = wm * 32 + mt * 16 + rsel * 8 + qrow;
                    __half* sr = stg + row * STG_ROW_H + ncol;
                    #pragma unroll
                    for (int nt = 0; nt < 7; nt++) {
                        float vx = d[mt][nt][rsel * 2 + 0] + bb[nt].x;
                        float vy = d[mt][nt][rsel * 2 + 1] + bb[nt].y;
                        *(half2*)(sr + nt * 8) = __floats2half2_rn(vx, vy);
                    }
                }
            }
        }
        __syncthreads();

        // --- coalesced writeback: warp w -> rows w*8..+7 (448B rows) ---
        if (l < 28) {
            #pragma unroll
            for (int r = 0; r < 8; r++) {
                int row = w * 8 + r;
                int gp = p0 + row;
                if (gp < N_POS) {
                    uint4 v = *(const uint4*)(stg + row * STG_ROW_H + l * 8);
                    *(uint4*)(yb + (size_t)gp * K_CH + l * 8) = v;
                }
            }
        }
        __syncthreads();
    }
}

// ---------------------------------------------------------------------------
// Kernel 2: gather (R10 batched-MLP version, 129us, near random-access BW).
// ---------------------------------------------------------------------------
#define GM 256

__global__ void __launch_bounds__(256, 3)
gather_kernel(const int* __restrict__ top,
              const int* __restrict__ down,
              float* __restrict__ out)
{
    __shared__ float smx[GM][33];
    const int b    = blockIdx.y;
    const int m0   = blockIdx.x * GM;
    const int tid  = threadIdx.x;
    const int lane = tid & 31;
    const int w    = tid >> 5;
    const int g8   = lane >> 2;    // 0..7 : m within octet
    const int l4   = lane & 3;     // 0..3 : uint4 slot (8 halves)

    const __half* yb = g_y + (size_t)b * N_POS * K_CH;

    // --- phase 1: index loads (batched) ---
    int jx[4], jy[4];
    #pragma unroll
    for (int i = 0; i < 4; i++) {
        int m = m0 + w * 32 + i * 8 + g8;
        jx[i] = -1; jy[i] = -1;
        if (m < NEW_N) {
            if (m < N_POS) {
                jx[i] = __ldg(top + m);
            } else {
                int2 jj = *(const int2*)(down + 2 * (m - N_POS));
                jx[i] = jj.x; jy[i] = jj.y;
            }
        }
    }

    // --- phase 2: value loads (up to 8 uint4 in flight) ---
    uint4 v0[4], v1[4];
    #pragma unroll
    for (int i = 0; i < 4; i++) {
        v0[i] = make_uint4(0u, 0u, 0u, 0u);
        if (jx[i] >= 0) {
            int s = jx[i] / N_POS, p = jx[i] - s * N_POS;
            v0[i] = *(const uint4*)(yb + (size_t)p * K_CH + s * 32 + l4 * 8);
        }
    }
    #pragma unroll
    for (int i = 0; i < 4; i++) {
        if (jy[i] >= 0) {
            int s = jy[i] / N_POS, p = jy[i] - s * N_POS;
            v1[i] = *(const uint4*)(yb + (size_t)p * K_CH + s * 32 + l4 * 8);
        }
    }

    // --- phase 3: convert + STS ---
    #pragma unroll
    for (int i = 0; i < 4; i++) {
        int mm = w * 32 + i * 8 + g8;
        float vf[8];
        const half2* h0 = (const half2*)&v0[i];
        #pragma unroll
        for (int q = 0; q < 4; q++) {
            float2 f = __half22float2(h0[q]);
            vf[2 * q] = f.x; vf[2 * q + 1] = f.y;
        }
        if (jy[i] >= 0) {
            const half2* h1 = (const half2*)&v1[i];
            #pragma unroll
            for (int q = 0; q < 4; q++) {
                float2 f = __half22float2(h1[q]);
                vf[2 * q]     = 0.5f * (vf[2 * q] + f.x);
                vf[2 * q + 1] = 0.5f * (vf[2 * q + 1] + f.y);
            }
        }
        float* s = &smx[mm][l4 * 8];
        #pragma unroll
        for (int j = 0; j < 8; j++) s[j] = vf[j];
    }
    __syncthreads();

    // --- transpose write: out[b][o][m], float2 along m ---
    float* ob = out + (size_t)b * C_OUT * NEW_N;
    #pragma unroll
    for (int it = 0; it < C_OUT * (GM / 2) / 256; it++) {
        int idx = it * 256 + tid;
        int o = idx >> 7;
        int q = idx & 127;
        int m = m0 + 2 * q;
        if (m < NEW_N) {
            float2 v = make_float2(smx[2 * q][o], smx[2 * q + 1][o]);
            *(float2*)(ob + (size_t)o * NEW_N + m) = v;
        }
    }
}

// ---------------------------------------------------------------------------
extern "C" void kernel_launch(void* const* d_in, const int* in_sizes, int n_in,
                              void* d_out, int out_size)
{
    const float* x    = (const float*)d_in[0];
    const float* W    = (const float*)d_in[1];
    const float* bias = (const float*)d_in[2];
    const int*   top  = (const int*)d_in[3];
    const int*   down = (const int*)d_in[4];
    float* out = (float*)d_out;

    cudaFuncSetAttribute(gemm_hmma_kernel,
                         cudaFuncAttributeMaxDynamicSharedMemorySize, SM_TOTAL);

    gemm_hmma_kernel<<<GEMM_GRID, GEMM_THREADS, SM_TOTAL>>>(x, W, bias);

    dim3 g2((NEW_N + GM - 1) / GM, B_SZ);   // (641, 16)
    gather_kernel<<<g2, 256>>>(top, down, out);
}